// round 2
// baseline (speedup 1.0000x reference)
#include <cuda_runtime.h>
#include <cstdint>

// Problem constants (fixed shapes from setup_inputs: B=4, N=1000, H=W=256)
#define BATCH 4
#define NBOX  1000
#define HW    65536          // 256*256
#define MAXD  100
#define NW    32             // 32 x uint32 words cover 1024 >= NBOX bits
#define MIN_AREA 25.0f
#define IOU_T    0.3f

static_assert(NW * 32 >= NBOX, "bitmask words must cover NBOX");

// ---------------- scratch (static device globals; no allocation) -------------
__device__ float    g_bs[BATCH * NBOX * 4];   // sorted boxes (score-desc order)
__device__ float    g_as[BATCH * NBOX];       // sorted areas
__device__ int      g_vs[BATCH * NBOX];       // sorted valid flags
__device__ int      g_ord[BATCH * NBOX];      // sorted -> original index
__device__ unsigned g_M [BATCH * NBOX * NW];  // IoU>thresh bitmask (j>i only)
__device__ int      g_fi[BATCH * MAXD];       // selected original indices, -1 = pad

// ---------------- kernel 1: stable rank-sort by masked score -----------------
// One block per batch, 256 threads. rank(i) = #{j : key_j > key_i} +
// #{j : key_j == key_i && j < i}  == stable descending argsort, matching
// jnp.argsort(-masked_score) (stable; invalid boxes keyed -inf go last,
// tied by original index).
__global__ void sort_kernel(const float* __restrict__ boxes,
                            const float* __restrict__ scores) {
    const int b = blockIdx.x;
    __shared__ float s_key[NBOX];
    const float4* bb = reinterpret_cast<const float4*>(boxes) + b * NBOX;
    const float*  ss = scores + b * NBOX;

    float4 mybox[4]; float myarea[4]; int myvalid[4]; float mykey[4];
    const float NEG_INF = __int_as_float(0xff800000u);

    #pragma unroll
    for (int k = 0; k < 4; k++) {
        int i = threadIdx.x + k * 256;
        if (i < NBOX) {
            float4 bx = bb[i];
            float area = (bx.z - bx.x) * (bx.w - bx.y);
            int   valid = area > MIN_AREA;
            float key = valid ? ss[i] : NEG_INF;
            mybox[k] = bx; myarea[k] = area; myvalid[k] = valid; mykey[k] = key;
            s_key[i] = key;
        }
    }
    __syncthreads();

    #pragma unroll
    for (int k = 0; k < 4; k++) {
        int i = threadIdx.x + k * 256;
        if (i < NBOX) {
            float ki = mykey[k];
            int rank = 0;
            for (int j = 0; j < NBOX; j++) {
                float kj = s_key[j];
                rank += (kj > ki) || (kj == ki && j < i);
            }
            if (rank < NBOX) {                    // always true; defensive
                int o = b * NBOX + rank;
                reinterpret_cast<float4*>(g_bs)[o] = mybox[k];
                g_as[o]  = myarea[k];
                g_vs[o]  = myvalid[k];
                g_ord[o] = i;
            }
        }
    }
}

// ---------------- kernel 2: IoU suppression bitmask --------------------------
// thread t -> (b, i, word w). bit jj set iff j=w*32+jj > i and IoU(i,j)>0.3.
__global__ void iou_kernel() {
    int t = blockIdx.x * blockDim.x + threadIdx.x;
    if (t >= BATCH * NBOX * NW) return;
    int b = t / (NBOX * NW);
    int r = t - b * NBOX * NW;
    int i = r >> 5;
    int w = r & 31;

    const float4* bs = reinterpret_cast<const float4*>(g_bs) + b * NBOX;
    const float*  as = g_as + b * NBOX;
    float4 bi = bs[i];
    float  ai = as[i];

    unsigned bits = 0;
    int j0 = w << 5;
    #pragma unroll 8
    for (int jj = 0; jj < 32; jj++) {
        int j = j0 + jj;
        if (j < NBOX && j > i) {
            float4 bj = bs[j];
            float lx = fmaxf(bi.x, bj.x), ly = fmaxf(bi.y, bj.y);
            float rx = fminf(bi.z, bj.z), ry = fminf(bi.w, bj.w);
            float ww = fmaxf(rx - lx, 0.0f), hh = fmaxf(ry - ly, 0.0f);
            float inter = ww * hh;
            float denom = ai + as[j] - inter;
            // IEEE round-to-nearest division regardless of fast-math flags:
            float iou = (denom > 0.0f) ? __fdiv_rn(inter, denom) : 0.0f;
            if (iou > IOU_T) bits |= (1u << jj);
        }
    }
    g_M[t] = bits;  // t == (b*NBOX + i)*NW + w
}

// ---------------- kernel 3: greedy sequential scan (1 warp / batch) ----------
// Lane L owns suppression word L (bits for sorted indices [32L, 32L+32)).
// One shfl per step fetches the (valid & ~suppressed) word covering the
// cursor; __ffs skip-ahead over dead words; early exit at MAXD kept.
__global__ void nms_scan_kernel() {
    const int b = blockIdx.x;
    const int lane = threadIdx.x;

    unsigned validw = 0;
    #pragma unroll
    for (int jj = 0; jj < 32; jj++) {
        int j = (lane << 5) + jj;
        if (j < NBOX && g_vs[b * NBOX + j]) validw |= (1u << jj);
    }

    unsigned remv = 0;
    int count = 0;
    int i = 0;
    while (i < NBOX && count < MAXD) {
        int wi = i >> 5;
        unsigned kw = __shfl_sync(0xffffffffu, validw & ~remv, wi);
        unsigned lowmask = (i & 31) ? ((1u << (i & 31)) - 1u) : 0u;
        kw &= ~lowmask;
        if (!kw) { i = (wi + 1) << 5; continue; }
        int p = __ffs(kw) - 1;
        i = (wi << 5) + p;                     // next kept (valid & unsuppressed)
        remv |= g_M[(b * NBOX + i) * NW + lane];
        if (lane == 0) g_fi[b * MAXD + count] = g_ord[b * NBOX + i];
        count++;
        i++;
    }
    if (lane == 0) {
        for (int k = count; k < MAXD; k++) g_fi[b * MAXD + k] = -1;
    }
}

// ---------------- kernel 4: mask gather (bandwidth-dominant) -----------------
// out_masks layout [B,100,H,W] f32, contiguous after boxes region.
__global__ void mask_gather_kernel(const float* __restrict__ masks,
                                   float* __restrict__ out_masks) {
    long long t = (long long)blockIdx.x * blockDim.x + threadIdx.x;
    const long long total = (long long)BATCH * MAXD * (HW / 4);
    if (t >= total) return;
    int slot = (int)(t / (HW / 4));         // b*100 + k
    int off  = (int)(t % (HW / 4));
    int fi = g_fi[slot];
    float4 v = make_float4(0.f, 0.f, 0.f, 0.f);
    if (fi >= 0 && fi < NBOX) {
        int b = slot / MAXD;
        v = reinterpret_cast<const float4*>(masks)
                [(long long)(b * NBOX + fi) * (HW / 4) + off];
    }
    reinterpret_cast<float4*>(out_masks)[t] = v;
}

// ---------------- kernel 5: boxes / scores / labels / valid ------------------
__global__ void scalars_kernel(const float* __restrict__ boxes,
                               const float* __restrict__ scores,
                               const void*  __restrict__ labels,
                               float* __restrict__ out) {
    int t = blockIdx.x * blockDim.x + threadIdx.x;
    if (t >= BATCH * MAXD) return;
    int b  = t / MAXD;
    int fi = g_fi[t];

    // Runtime dtype probe: jnp's int64 silently demotes to int32 when x64 is
    // disabled, so the labels buffer may be either width. Little-endian int64
    // labels in [0,91) have every odd 32-bit word == 0.
    // P(false positive | int32 labels) = (1/91)^64 ~ 0.
    const int* l32 = reinterpret_cast<const int*>(labels);
    bool i64 = true;
    #pragma unroll 16
    for (int k = 0; k < 64; k++) {
        i64 = i64 && (l32[2 * k + 1] == 0);
    }

    float4 bx = make_float4(0.f, 0.f, 0.f, 0.f);
    float  sc = 0.f, lb = -1.f, vd = 0.f;
    if (fi >= 0 && fi < NBOX) {
        int src = b * NBOX + fi;
        bx = reinterpret_cast<const float4*>(boxes)[src];
        sc = scores[src];
        long long lv = i64 ? reinterpret_cast<const long long*>(labels)[src]
                           : (long long)l32[src];
        lb = (float)lv;
        vd = 1.0f;
    }

    const int BOX0 = 0;
    const int SC0  = BATCH * MAXD * 4 + BATCH * MAXD * HW;   // after boxes+masks
    const int LB0  = SC0 + BATCH * MAXD;
    const int VD0  = LB0 + BATCH * MAXD;

    reinterpret_cast<float4*>(out + BOX0)[t] = bx;
    out[SC0 + t] = sc;
    out[LB0 + t] = lb;
    out[VD0 + t] = vd;
}

// ---------------- launch ------------------------------------------------------
extern "C" void kernel_launch(void* const* d_in, const int* in_sizes, int n_in,
                              void* d_out, int out_size) {
    const float* boxes  = (const float*)d_in[0];   // [B,N,4]   f32
    const float* masks  = (const float*)d_in[1];   // [B,N,1,H,W] f32
    const float* scores = (const float*)d_in[2];   // [B,N]     f32
    const void*  labels = d_in[3];                 // [B,N]     i32 or i64
    float* out = (float*)d_out;

    sort_kernel<<<BATCH, 256>>>(boxes, scores);

    int iou_threads = BATCH * NBOX * NW;           // 128000
    iou_kernel<<<(iou_threads + 255) / 256, 256>>>();

    nms_scan_kernel<<<BATCH, 32>>>();

    float* out_masks = out + (size_t)BATCH * MAXD * 4;
    long long m4 = (long long)BATCH * MAXD * (HW / 4);   // 6,553,600 float4s
    mask_gather_kernel<<<(unsigned)((m4 + 255) / 256), 256>>>(masks, out_masks);

    scalars_kernel<<<(BATCH * MAXD + 255) / 256, 256>>>(boxes, scores, labels, out);
}

// round 4
// speedup vs baseline: 1.8563x; 1.8563x over previous
#include <cuda_runtime.h>
#include <cstdint>

// Problem constants (fixed shapes from setup_inputs: B=4, N=1000, H=W=256)
#define BATCH 4
#define NBOX  1000
#define HW    65536          // 256*256
#define MAXD  100
#define NW    32             // 32 x uint32 words cover 1024 >= NBOX bits
#define MIN_AREA 25.0f
#define IOU_T    0.3f

static_assert(NW * 32 >= NBOX, "bitmask words must cover NBOX");
static_assert(NBOX % 4 == 0, "float4 key loop");

// ---------------- scratch (static device globals; no allocation) -------------
__device__ float    g_bs[BATCH * NBOX * 4];                 // sorted boxes
__device__ float    g_as[BATCH * NBOX];                     // sorted areas
__device__ int      g_vs[BATCH * NBOX];                     // sorted valid flags
__device__ int      g_ord[BATCH * NBOX];                    // sorted -> original
__device__ __align__(16) unsigned g_M[BATCH * NBOX * NW];   // IoU bitmask [b][i][w]
__device__ int      g_fi[BATCH * MAXD];                     // selected orig idx, -1 pad

// ---------------- kernel 1: stable rank-sort by masked score -----------------
// grid (4, BATCH): 4 blocks x 256 threads cover 1000 rows per batch. Each block
// stages all keys+boxes in shared; rank(i) = #{key_j > key_i} + #{tie, j < i}
// == stable descending argsort (matches jnp.argsort(-masked_score)).
__global__ void sort_kernel(const float* __restrict__ boxes,
                            const float* __restrict__ scores) {
    const int b = blockIdx.y;
    __shared__ float4 s_box[NBOX];
    __shared__ float  s_key[NBOX];
    const float4* bb = reinterpret_cast<const float4*>(boxes) + b * NBOX;
    const float*  ss = scores + b * NBOX;
    const float NEG_INF = __int_as_float(0xff800000u);

    for (int j = threadIdx.x; j < NBOX; j += 256) {
        float4 bx = bb[j];
        float area = (bx.z - bx.x) * (bx.w - bx.y);
        s_box[j] = bx;
        s_key[j] = (area > MIN_AREA) ? ss[j] : NEG_INF;
    }
    __syncthreads();

    int i = blockIdx.x * 256 + threadIdx.x;
    if (i >= NBOX) return;
    float ki = s_key[i];
    const float4* k4 = reinterpret_cast<const float4*>(s_key);
    int rank = 0;
    #pragma unroll 5
    for (int g = 0; g < NBOX / 4; g++) {
        float4 k = k4[g];
        int j = 4 * g;
        rank += (k.x > ki) || (k.x == ki && (j + 0) < i);
        rank += (k.y > ki) || (k.y == ki && (j + 1) < i);
        rank += (k.z > ki) || (k.z == ki && (j + 2) < i);
        rank += (k.w > ki) || (k.w == ki && (j + 3) < i);
    }
    float4 bx = s_box[i];
    int o = b * NBOX + rank;
    reinterpret_cast<float4*>(g_bs)[o] = bx;
    g_as[o]  = (bx.z - bx.x) * (bx.w - bx.y);
    g_vs[o]  = (ki != NEG_INF);
    g_ord[o] = i;
}

// ---------------- kernel 2: IoU suppression bitmask (transposed map) ---------
// t -> (b, w, i): a warp holds ONE word w and 32 consecutive rows i, so fully
// lower-triangle warps (i >= 32w+32 for all lanes) exit immediately instead of
// issuing predicated-dead iterations. bj/aj are warp-uniform loads.
__global__ void iou_kernel() {
    int t = blockIdx.x * blockDim.x + threadIdx.x;
    if (t >= BATCH * NW * NBOX) return;
    int i = t % NBOX;
    int w = (t / NBOX) % NW;
    int b = t / (NBOX * NW);

    if (i >= (w << 5) + 32) return;        // row entirely below this word

    const float4* bs = reinterpret_cast<const float4*>(g_bs) + b * NBOX;
    const float*  as = g_as + b * NBOX;
    float4 bi = bs[i];
    float  ai = as[i];
    int di = i - (w << 5);                 // >=0 only in the diagonal word

    unsigned bits = 0;
    int j0 = w << 5;
    #pragma unroll 4
    for (int jj = 0; jj < 32; jj++) {
        int j = j0 + jj;
        if (j < NBOX && jj > di) {         // di<0 off-diagonal -> always true
            float4 bj = bs[j];
            float lx = fmaxf(bi.x, bj.x), ly = fmaxf(bi.y, bj.y);
            float rx = fminf(bi.z, bj.z), ry = fminf(bi.w, bj.w);
            float ww = fmaxf(rx - lx, 0.0f), hh = fmaxf(ry - ly, 0.0f);
            float inter = ww * hh;
            bool sup = false;
            if (inter > 0.0f) {
                float denom = as[j] + ai - inter;   // > 0 (areas positive)
                // Fast approx divide; exact __fdiv_rn fallback only inside a
                // +-1e-4 band around the threshold (keeps decisions bit-exact
                // vs the reference's rn division, ~a handful of pairs total).
                float est = __fdividef(inter, denom);
                if (est > IOU_T + 1e-4f)      sup = true;
                else if (est >= IOU_T - 1e-4f)
                    sup = (__fdiv_rn(inter, denom) > IOU_T);
            }
            if (sup) bits |= (1u << jj);
        }
    }
    g_M[(b * NBOX + i) * NW + w] = bits;
}

// ---------------- kernel 3: greedy scan, mask staged in shared ---------------
// One block per batch, 1024 threads. Stage the 125 KB suppression matrix and
// validity words into shared, then warp 0 does the serial scan with 29-cycle
// LDS instead of ~234-cycle L2 loads. Dynamic smem set via FuncAttribute.
__global__ void nms_scan_kernel() {
    extern __shared__ unsigned s_mem[];          // [NBOX*NW] mask + [32] valid
    unsigned* s_M = s_mem;
    unsigned* s_valid = s_mem + NBOX * NW;

    const int b = blockIdx.x;
    const int tid = threadIdx.x;
    const int lane = tid & 31;
    const int warp = tid >> 5;

    // stage mask (uint4 coalesced): 32000 words = 8000 uint4
    const uint4* src = reinterpret_cast<const uint4*>(g_M + b * NBOX * NW);
    uint4* dst = reinterpret_cast<uint4*>(s_M);
    for (int k = tid; k < NBOX * NW / 4; k += 1024) dst[k] = src[k];

    // validity words via ballot: warp W covers sorted indices [32W, 32W+32)
    int j = tid;
    int v = (j < NBOX) ? g_vs[b * NBOX + j] : 0;
    unsigned bw = __ballot_sync(0xffffffffu, v);
    if (lane == 0) s_valid[warp] = bw;
    __syncthreads();

    if (warp != 0) return;
    unsigned validw = s_valid[lane];
    unsigned remv = 0;
    int count = 0;
    int i = 0;
    while (i < NBOX && count < MAXD) {
        int wi = i >> 5;
        unsigned kw = __shfl_sync(0xffffffffu, validw & ~remv, wi);
        unsigned lowmask = (i & 31) ? ((1u << (i & 31)) - 1u) : 0u;
        kw &= ~lowmask;
        if (!kw) { i = (wi + 1) << 5; continue; }
        int p = __ffs(kw) - 1;
        i = (wi << 5) + p;                        // next kept box
        remv |= s_M[i * NW + lane];
        if (lane == 0) g_fi[b * MAXD + count] = g_ord[b * NBOX + i];
        count++;
        i++;
    }
    if (lane == 0) {
        for (int k = count; k < MAXD; k++) g_fi[b * MAXD + k] = -1;
    }
}

// ---------------- kernel 4: mask gather (bandwidth-dominant) -----------------
// grid (16, 400): blockIdx.y = output slot (b*100+k), blockIdx.x = 16KB chunk.
// 4 independent float4 per thread (MLP=4), streaming load/store hints.
__global__ void mask_gather_kernel(const float* __restrict__ masks,
                                   float* __restrict__ out_masks) {
    const int slot = blockIdx.y;                  // 0..399
    const int fi = g_fi[slot];                    // warp-uniform
    const int base = blockIdx.x * 1024 + threadIdx.x;   // float4 index in slot
    float4* outp = reinterpret_cast<float4*>(out_masks) +
                   (long long)slot * (HW / 4);

    if (fi >= 0) {
        const int b = slot / MAXD;
        const float4* srcp = reinterpret_cast<const float4*>(masks) +
                             (long long)(b * NBOX + fi) * (HW / 4);
        float4 v0 = __ldcs(srcp + base + 0 * 256);
        float4 v1 = __ldcs(srcp + base + 1 * 256);
        float4 v2 = __ldcs(srcp + base + 2 * 256);
        float4 v3 = __ldcs(srcp + base + 3 * 256);
        __stcs(outp + base + 0 * 256, v0);
        __stcs(outp + base + 1 * 256, v1);
        __stcs(outp + base + 2 * 256, v2);
        __stcs(outp + base + 3 * 256, v3);
    } else {
        float4 z = make_float4(0.f, 0.f, 0.f, 0.f);
        __stcs(outp + base + 0 * 256, z);
        __stcs(outp + base + 1 * 256, z);
        __stcs(outp + base + 2 * 256, z);
        __stcs(outp + base + 3 * 256, z);
    }
}

// ---------------- kernel 5: boxes / scores / labels / valid ------------------
__global__ void scalars_kernel(const float* __restrict__ boxes,
                               const float* __restrict__ scores,
                               const void*  __restrict__ labels,
                               float* __restrict__ out) {
    int t = blockIdx.x * blockDim.x + threadIdx.x;
    if (t >= BATCH * MAXD) return;
    int b  = t / MAXD;
    int fi = g_fi[t];

    // Runtime dtype probe: jnp int64 silently demotes to int32 when x64 is
    // disabled. Little-endian int64 labels in [0,91) have every odd 32-bit
    // word == 0. P(false positive | int32) = (1/91)^64 ~ 0.
    const int* l32 = reinterpret_cast<const int*>(labels);
    bool i64 = true;
    #pragma unroll 16
    for (int k = 0; k < 64; k++) i64 = i64 && (l32[2 * k + 1] == 0);

    float4 bx = make_float4(0.f, 0.f, 0.f, 0.f);
    float  sc = 0.f, lb = -1.f, vd = 0.f;
    if (fi >= 0 && fi < NBOX) {
        int src = b * NBOX + fi;
        bx = reinterpret_cast<const float4*>(boxes)[src];
        sc = scores[src];
        long long lv = i64 ? reinterpret_cast<const long long*>(labels)[src]
                           : (long long)l32[src];
        lb = (float)lv;
        vd = 1.0f;
    }

    const int BOX0 = 0;
    const int SC0  = BATCH * MAXD * 4 + BATCH * MAXD * HW;   // after boxes+masks
    const int LB0  = SC0 + BATCH * MAXD;
    const int VD0  = LB0 + BATCH * MAXD;

    reinterpret_cast<float4*>(out + BOX0)[t] = bx;
    out[SC0 + t] = sc;
    out[LB0 + t] = lb;
    out[VD0 + t] = vd;
}

// ---------------- launch ------------------------------------------------------
extern "C" void kernel_launch(void* const* d_in, const int* in_sizes, int n_in,
                              void* d_out, int out_size) {
    const float* boxes  = (const float*)d_in[0];   // [B,N,4]     f32
    const float* masks  = (const float*)d_in[1];   // [B,N,1,H,W] f32
    const float* scores = (const float*)d_in[2];   // [B,N]       f32
    const void*  labels = d_in[3];                 // [B,N]       i32 or i64
    float* out = (float*)d_out;

    const int scan_smem = (NBOX * NW + 32) * (int)sizeof(unsigned);  // ~125 KB
    // Persistent per-function attribute; also applied on the pre-capture
    // correctness call, so the captured launches are always valid.
    (void)cudaFuncSetAttribute(nms_scan_kernel,
                               cudaFuncAttributeMaxDynamicSharedMemorySize,
                               scan_smem);

    sort_kernel<<<dim3(4, BATCH), 256>>>(boxes, scores);

    int iou_threads = BATCH * NW * NBOX;           // 128000
    iou_kernel<<<(iou_threads + 255) / 256, 256>>>();

    nms_scan_kernel<<<BATCH, 1024, scan_smem>>>();

    float* out_masks = out + (size_t)BATCH * MAXD * 4;
    mask_gather_kernel<<<dim3(HW / 4 / 1024, BATCH * MAXD), 256>>>(masks, out_masks);

    scalars_kernel<<<(BATCH * MAXD + 255) / 256, 256>>>(boxes, scores, labels, out);
}

// round 5
// speedup vs baseline: 2.0344x; 1.0960x over previous
#include <cuda_runtime.h>
#include <cstdint>

// Fixed shapes from setup_inputs: B=4, N=1000, H=W=256
#define BATCH 4
#define NBOX  1000
#define HW    65536
#define MAXD  100
#define NW    32              // 32 x u32 words cover 1024 >= NBOX bits
#define MIN_AREA 25.0f
#define IOU_T    0.3f

#define NMASTER BATCH          // blocks 0..3  : sort + scan + scalar outputs
#define NWORK   125            // blocks 4..128: IoU bitmask (125*1024 = 128000 items)
#define FGRID   (NMASTER + NWORK)
#define TPB     1024
#define SORT_M  1024           // bitonic size (>= NBOX)

static_assert(NW * 32 >= NBOX, "bitmask words must cover NBOX");
static_assert(NWORK * TPB == BATCH * NW * NBOX, "worker item count");

// ---------------- scratch (static device globals; zero-init at load) ---------
__device__ float    g_bs[BATCH * NBOX * 4];                 // sorted boxes
__device__ float    g_as[BATCH * NBOX];                     // sorted areas
__device__ __align__(16) unsigned g_M[BATCH * NBOX * NW];   // IoU bitmask [b][i][w]
__device__ int      g_fi[BATCH * MAXD];                     // kept orig idx, -1 pad
__device__ int      g_cnt_sort;                             // 0..BATCH
__device__ int      g_cnt_iou;                              // 0..NWORK
__device__ int      g_cnt_done;                             // 0..BATCH

// dynamic smem word layout (masters; workers ignore it):
//   [0 .. 31999]      s_M   (aliased during sort: first 2048 words = u64 keys[1024])
//   [32000 .. 32031]  s_valid
//   [32032 .. 33055]  s_ord
//   [33056 .. 33155]  s_fi
#define SMEM_WORDS (NBOX * NW + 32 + SORT_M + MAXD)

__device__ __forceinline__ unsigned float_ordered(float f) {
    unsigned u = __float_as_uint(f);
    return (u & 0x80000000u) ? ~u : (u | 0x80000000u);   // ascending == float asc
}

// ================= fused kernel: sort + IoU + scan + scalars =================
__global__ __launch_bounds__(TPB, 1)
void fused_kernel(const float* __restrict__ boxes,
                  const float* __restrict__ scores,
                  const void*  __restrict__ labels,
                  float* __restrict__ out) {
    extern __shared__ unsigned s_mem[];
    const int tid = threadIdx.x;

    if (blockIdx.x >= NMASTER) {
        // ---------------- IoU worker: t -> (b, w, i), exact R3 body ----------
        if (tid == 0) {
            while (atomicAdd(&g_cnt_sort, 0) < BATCH) __nanosleep(64);
            __threadfence();
        }
        __syncthreads();

        int t = (blockIdx.x - NMASTER) * TPB + tid;      // 0..127999
        int i = t % NBOX;
        int w = (t / NBOX) % NW;
        int b = t / (NBOX * NW);

        if (i < (w << 5) + 32) {        // rows fully below word w never written
            const float4* bs = reinterpret_cast<const float4*>(g_bs) + b * NBOX;
            const float*  as = g_as + b * NBOX;
            float4 bi = bs[i];
            float  ai = as[i];
            int di = i - (w << 5);      // >= 0 only in the diagonal word

            unsigned bits = 0;
            int j0 = w << 5;
            #pragma unroll 4
            for (int jj = 0; jj < 32; jj++) {
                int j = j0 + jj;
                if (j < NBOX && jj > di) {
                    float4 bj = bs[j];
                    float lx = fmaxf(bi.x, bj.x), ly = fmaxf(bi.y, bj.y);
                    float rx = fminf(bi.z, bj.z), ry = fminf(bi.w, bj.w);
                    float ww = fmaxf(rx - lx, 0.0f), hh = fmaxf(ry - ly, 0.0f);
                    float inter = ww * hh;
                    bool sup = false;
                    if (inter > 0.0f) {
                        float denom = as[j] + ai - inter;    // > 0
                        float est = __fdividef(inter, denom);
                        if (est > IOU_T + 1e-4f)       sup = true;
                        else if (est >= IOU_T - 1e-4f)
                            sup = (__fdiv_rn(inter, denom) > IOU_T);
                    }
                    if (sup) bits |= (1u << jj);
                }
            }
            g_M[(b * NBOX + i) * NW + w] = bits;
        }
        __threadfence();
        __syncthreads();
        if (tid == 0) atomicAdd(&g_cnt_iou, 1);
        return;
    }

    // ======================= master block: one batch =========================
    const int b = blockIdx.x;
    unsigned* s_M     = s_mem;
    unsigned* s_valid = s_mem + NBOX * NW;
    unsigned* s_ord   = s_valid + 32;
    int*      s_fi    = reinterpret_cast<int*>(s_ord + SORT_M);
    unsigned long long* s_k = reinterpret_cast<unsigned long long*>(s_mem);

    const float4* bb = reinterpret_cast<const float4*>(boxes) + b * NBOX;
    const float*  ss = scores + b * NBOX;

    // ---- phase 1: build packed keys, bitonic ascending sort -----------------
    // key64 = (~orderedFloat(masked_score) << 32) | idx  ==>  ascending sort
    // equals stable descending argsort (ties broken by ascending index).
    {
        unsigned long long key = ~0ULL;                  // pad slots sort last
        if (tid < NBOX) {
            float4 bx = bb[tid];
            float area = (bx.z - bx.x) * (bx.w - bx.y);
            float k = (area > MIN_AREA) ? ss[tid]
                                        : __int_as_float(0xff800000u);
            key = ((unsigned long long)(~float_ordered(k)) << 32) |
                  (unsigned)tid;
        }
        s_k[tid] = key;
        for (int k = 2; k <= SORT_M; k <<= 1) {
            for (int j = k >> 1; j > 0; j >>= 1) {
                __syncthreads();
                int ixj = tid ^ j;
                if (ixj > tid) {
                    bool asc = ((tid & k) == 0);
                    unsigned long long a = s_k[tid], c = s_k[ixj];
                    if ((a > c) == asc) { s_k[tid] = c; s_k[ixj] = a; }
                }
            }
        }
        __syncthreads();
    }

    // ---- phase 2: publish sorted boxes/areas, keep ord/valid in smem --------
    {
        bool val = false;
        unsigned myi = 0;
        if (tid < NBOX) {
            myi = (unsigned)(s_k[tid] & 0xFFFFFFFFu);
            float4 bx = bb[myi];
            float area = (bx.z - bx.x) * (bx.w - bx.y);
            val = (area > MIN_AREA);
            int o = b * NBOX + tid;
            reinterpret_cast<float4*>(g_bs)[o] = bx;
            g_as[o] = area;
        }
        unsigned bw = __ballot_sync(0xffffffffu, val);
        __syncthreads();                    // s_k reads done before s_ord alias? (s_ord separate region)
        if ((tid & 31) == 0) s_valid[tid >> 5] = bw;
        if (tid < NBOX) s_ord[tid] = myi; else if (tid < SORT_M) s_ord[tid] = 0;
    }
    __threadfence();
    __syncthreads();
    if (tid == 0) atomicAdd(&g_cnt_sort, 1);

    // ---- phase 3: wait for all IoU workers; counter reset dance -------------
    if (tid == 0) {
        while (atomicAdd(&g_cnt_iou, 0) < NWORK) __nanosleep(64);
        atomicAdd(&g_cnt_done, 1);
        if (b == 0) {
            while (atomicAdd(&g_cnt_done, 0) < BATCH) __nanosleep(64);
            atomicExch(&g_cnt_sort, 0);     // restore zero for next replay
            atomicExch(&g_cnt_iou, 0);
            atomicExch(&g_cnt_done, 0);
        }
        __threadfence();
    }
    __syncthreads();

    // ---- phase 4: stage mask into shared, warp-0 greedy scan ----------------
    {
        const uint4* src = reinterpret_cast<const uint4*>(g_M + b * NBOX * NW);
        uint4* dst = reinterpret_cast<uint4*>(s_M);
        for (int k = tid; k < NBOX * NW / 4; k += TPB) dst[k] = src[k];
    }
    __syncthreads();

    if ((tid >> 5) == 0) {
        const int lane = tid;
        unsigned validw = s_valid[lane];
        unsigned remv = 0;
        int count = 0;
        int i = 0;
        while (i < NBOX && count < MAXD) {
            int wi = i >> 5;
            unsigned kw = __shfl_sync(0xffffffffu, validw & ~remv, wi);
            unsigned lowmask = (i & 31) ? ((1u << (i & 31)) - 1u) : 0u;
            kw &= ~lowmask;
            if (!kw) { i = (wi + 1) << 5; continue; }
            int p = __ffs(kw) - 1;
            i = (wi << 5) + p;                       // next kept box
            remv |= s_M[i * NW + lane];
            if (lane == 0) {
                int fi = (int)s_ord[i];
                s_fi[count] = fi;
                g_fi[b * MAXD + count] = fi;
            }
            count++;
            i++;
        }
        if (lane == 0) {
            for (int k = count; k < MAXD; k++) {
                s_fi[k] = -1;
                g_fi[b * MAXD + k] = -1;
            }
        }
    }
    __syncthreads();

    // ---- phase 5: scalar outputs (boxes/scores/labels/valid) ----------------
    // Label dtype probe: jnp int64 silently demotes to int32 when x64 is off.
    // LE int64 labels in [0,91) => every odd 32-bit word is 0.
    const int* l32 = reinterpret_cast<const int*>(labels);
    bool myok = (tid < 64) ? (l32[2 * tid + 1] == 0) : true;
    bool i64 = __syncthreads_and(myok);

    if (tid < MAXD) {
        int t = b * MAXD + tid;
        int fi = s_fi[tid];
        float4 bx = make_float4(0.f, 0.f, 0.f, 0.f);
        float  sc = 0.f, lb = -1.f, vd = 0.f;
        if (fi >= 0) {
            int src = b * NBOX + fi;
            bx = reinterpret_cast<const float4*>(boxes)[src];
            sc = scores[src];
            long long lv = i64 ? reinterpret_cast<const long long*>(labels)[src]
                               : (long long)l32[src];
            lb = (float)lv;
            vd = 1.0f;
        }
        const int SC0 = BATCH * MAXD * 4 + BATCH * MAXD * HW;
        const int LB0 = SC0 + BATCH * MAXD;
        const int VD0 = LB0 + BATCH * MAXD;
        reinterpret_cast<float4*>(out)[t] = bx;
        out[SC0 + t] = sc;
        out[LB0 + t] = lb;
        out[VD0 + t] = vd;
    }
}

// ---------------- mask gather (bandwidth-dominant) ---------------------------
// grid (8, 400): blockIdx.y = slot, 8 float4 per thread (MLP=8), streaming.
__global__ void mask_gather_kernel(const float* __restrict__ masks,
                                   float* __restrict__ out_masks) {
    const int slot = blockIdx.y;
    const int fi = g_fi[slot];
    const int base = blockIdx.x * 2048 + threadIdx.x;     // float4 index in slot
    float4* outp = reinterpret_cast<float4*>(out_masks) +
                   (long long)slot * (HW / 4);

    if (fi >= 0) {
        const int b = slot / MAXD;
        const float4* srcp = reinterpret_cast<const float4*>(masks) +
                             (long long)(b * NBOX + fi) * (HW / 4);
        float4 v[8];
        #pragma unroll
        for (int k = 0; k < 8; k++) v[k] = __ldcs(srcp + base + k * 256);
        #pragma unroll
        for (int k = 0; k < 8; k++) __stcs(outp + base + k * 256, v[k]);
    } else {
        float4 z = make_float4(0.f, 0.f, 0.f, 0.f);
        #pragma unroll
        for (int k = 0; k < 8; k++) __stcs(outp + base + k * 256, z);
    }
}

// ---------------- launch ------------------------------------------------------
extern "C" void kernel_launch(void* const* d_in, const int* in_sizes, int n_in,
                              void* d_out, int out_size) {
    const float* boxes  = (const float*)d_in[0];   // [B,N,4]     f32
    const float* masks  = (const float*)d_in[1];   // [B,N,1,H,W] f32
    const float* scores = (const float*)d_in[2];   // [B,N]       f32
    const void*  labels = d_in[3];                 // [B,N]       i32 or i64
    float* out = (float*)d_out;

    const int fsmem = SMEM_WORDS * (int)sizeof(unsigned);   // ~132.6 KB
    (void)cudaFuncSetAttribute(fused_kernel,
                               cudaFuncAttributeMaxDynamicSharedMemorySize,
                               fsmem);

    fused_kernel<<<FGRID, TPB, fsmem>>>(boxes, scores, labels, out);

    float* out_masks = out + (size_t)BATCH * MAXD * 4;
    mask_gather_kernel<<<dim3(HW / 4 / 2048, BATCH * MAXD), 256>>>(masks, out_masks);
}